// round 2
// baseline (speedup 1.0000x reference)
#include <cuda_runtime.h>

#define N_NODES 100000
#define IN_CH   256
#define OUT_CH  128
#define N_EDGES 1600000
#define FULL_MASK 0xFFFFFFFFu

// ---------------- scratch (static device globals; no runtime alloc) ----------------
__device__ __align__(16) float g_xp[(size_t)N_NODES * OUT_CH];   // projected features
__device__ float g_asrc[N_NODES];
__device__ float g_adst[N_NODES];
__device__ int   g_count[N_NODES];
__device__ int   g_start[N_NODES];
__device__ int   g_cursor[N_NODES];
__device__ int   g_csr[N_EDGES];
__device__ int   g_base;

// ---------------- packed fp32x2 helpers (FFMA2) ----------------
__device__ __forceinline__ unsigned long long pack2(float lo, float hi) {
    unsigned long long r;
    asm("mov.b64 %0, {%1, %2};" : "=l"(r) : "f"(lo), "f"(hi));
    return r;
}
__device__ __forceinline__ void ffma2(unsigned long long& acc, unsigned long long a,
                                      unsigned long long b) {
    asm("fma.rn.f32x2 %0, %1, %2, %0;" : "+l"(acc) : "l"(a), "l"(b));
}
__device__ __forceinline__ float2 unpack2(unsigned long long v) {
    float2 f;
    asm("mov.b64 {%0, %1}, %2;" : "=f"(f.x), "=f"(f.y) : "l"(v));
    return f;
}

// ---------------- init: zero histogram + base cursor ----------------
__global__ void init_kernel() {
    int i = blockIdx.x * blockDim.x + threadIdx.x;
    if (i < N_NODES) g_count[i] = 0;
    if (i == 0) g_base = 0;
}

// ---------------- GEMM: xp = x @ W  (M=100000, K=256, N=128) ----------------
// 128x128 tile, BK=16, 256 threads, 8x8 per thread, f32x2 packed accumulators.
__global__ void __launch_bounds__(256) gemm_kernel(const float* __restrict__ X,
                                                   const float* __restrict__ W) {
    __shared__ float As[16][132];   // [k][m], padded
    __shared__ float Bs[16][128];   // [k][n]

    const int tid = threadIdx.x;
    const int tx = tid & 15;        // col group (8 cols each)
    const int ty = tid >> 4;        // row group (8 rows each)
    const int bm = blockIdx.x * 128;

    unsigned long long acc[8][4];
#pragma unroll
    for (int j = 0; j < 8; j++)
#pragma unroll
        for (int i = 0; i < 4; i++) acc[j][i] = 0ull;

    for (int k0 = 0; k0 < IN_CH; k0 += 16) {
        // load A tile (128 rows x 16 k) as 512 float4s, transpose into As[k][m]
#pragma unroll
        for (int t = 0; t < 2; t++) {
            int idx = tid + t * 256;
            int row = idx >> 2;
            int kq  = idx & 3;
            float4 v = make_float4(0.f, 0.f, 0.f, 0.f);
            if (bm + row < N_NODES)
                v = *(const float4*)&X[(size_t)(bm + row) * IN_CH + k0 + kq * 4];
            As[kq * 4 + 0][row] = v.x;
            As[kq * 4 + 1][row] = v.y;
            As[kq * 4 + 2][row] = v.z;
            As[kq * 4 + 3][row] = v.w;
        }
        // load B tile (16 k x 128 n)
#pragma unroll
        for (int t = 0; t < 2; t++) {
            int idx = tid + t * 256;
            int kk = idx >> 5;
            int nq = idx & 31;
            float4 v = *(const float4*)&W[(size_t)(k0 + kk) * OUT_CH + nq * 4];
            *(float4*)&Bs[kk][nq * 4] = v;
        }
        __syncthreads();

#pragma unroll
        for (int kk = 0; kk < 16; kk++) {
            float4 a0 = *(const float4*)&As[kk][ty * 8];
            float4 a1 = *(const float4*)&As[kk][ty * 8 + 4];
            float4 b0 = *(const float4*)&Bs[kk][tx * 8];
            float4 b1 = *(const float4*)&Bs[kk][tx * 8 + 4];
            unsigned long long bp[4] = {pack2(b0.x, b0.y), pack2(b0.z, b0.w),
                                        pack2(b1.x, b1.y), pack2(b1.z, b1.w)};
            float a[8] = {a0.x, a0.y, a0.z, a0.w, a1.x, a1.y, a1.z, a1.w};
#pragma unroll
            for (int j = 0; j < 8; j++) {
                unsigned long long ap = pack2(a[j], a[j]);
#pragma unroll
                for (int i = 0; i < 4; i++) ffma2(acc[j][i], ap, bp[i]);
            }
        }
        __syncthreads();
    }

    // store to g_xp
#pragma unroll
    for (int j = 0; j < 8; j++) {
        int row = bm + ty * 8 + j;
        if (row < N_NODES) {
            float2 o0 = unpack2(acc[j][0]);
            float2 o1 = unpack2(acc[j][1]);
            float2 o2 = unpack2(acc[j][2]);
            float2 o3 = unpack2(acc[j][3]);
            float4 v0 = make_float4(o0.x, o0.y, o1.x, o1.y);
            float4 v1 = make_float4(o2.x, o2.y, o3.x, o3.y);
            *(float4*)&g_xp[(size_t)row * OUT_CH + tx * 8]     = v0;
            *(float4*)&g_xp[(size_t)row * OUT_CH + tx * 8 + 4] = v1;
        }
    }
}

// ---------------- per-node attention logits ----------------
__global__ void alpha_kernel(const float* __restrict__ att_src,
                             const float* __restrict__ att_dst) {
    int gw   = (blockIdx.x * blockDim.x + threadIdx.x) >> 5;
    int lane = threadIdx.x & 31;
    if (gw >= N_NODES) return;
    float4 as4 = ((const float4*)att_src)[lane];
    float4 ad4 = ((const float4*)att_dst)[lane];
    float4 v   = ((const float4*)(g_xp + (size_t)gw * OUT_CH))[lane];
    float ps = v.x * as4.x + v.y * as4.y + v.z * as4.z + v.w * as4.w;
    float pd = v.x * ad4.x + v.y * ad4.y + v.z * ad4.z + v.w * ad4.w;
#pragma unroll
    for (int off = 16; off; off >>= 1) {
        ps += __shfl_xor_sync(FULL_MASK, ps, off);
        pd += __shfl_xor_sync(FULL_MASK, pd, off);
    }
    if (lane == 0) {
        g_asrc[gw] = ps;
        g_adst[gw] = pd;
    }
}

// ---------------- histogram over dst (drop self-edges); edge_index is int32 ----------------
__global__ void hist_kernel(const int* __restrict__ ei) {
    int e = blockIdx.x * blockDim.x + threadIdx.x;
    if (e >= N_EDGES) return;
    int s = ei[e];
    int d = ei[N_EDGES + e];
    if (s != d) atomicAdd(&g_count[d], 1);
}

// ---------------- scan: per-block scan + atomic block base ----------------
__global__ void scan_kernel() {
    __shared__ int sh[1024];
    __shared__ int sbase;
    int i = blockIdx.x * 1024 + threadIdx.x;
    int c = (i < N_NODES) ? g_count[i] : 0;
    sh[threadIdx.x] = c;
    __syncthreads();
#pragma unroll
    for (int off = 1; off < 1024; off <<= 1) {
        int v = 0;
        if ((int)threadIdx.x >= off) v = sh[threadIdx.x - off];
        __syncthreads();
        sh[threadIdx.x] += v;
        __syncthreads();
    }
    if (threadIdx.x == 1023) sbase = atomicAdd(&g_base, sh[1023]);
    __syncthreads();
    if (i < N_NODES) {
        int st = sbase + sh[threadIdx.x] - c;
        g_start[i]  = st;
        g_cursor[i] = st;
    }
}

// ---------------- scatter edges into CSR ----------------
__global__ void scatter_kernel(const int* __restrict__ ei) {
    int e = blockIdx.x * blockDim.x + threadIdx.x;
    if (e >= N_EDGES) return;
    int s = ei[e];
    int d = ei[N_EDGES + e];
    if (s != d) {
        int pos = atomicAdd(&g_cursor[d], 1);
        g_csr[pos] = s;
    }
}

// ---------------- fused softmax + weighted aggregation: one warp per dst ----------------
__global__ void __launch_bounds__(256) aggregate_kernel(const float* __restrict__ bias,
                                                        float* __restrict__ out) {
    int gw   = (blockIdx.x * blockDim.x + threadIdx.x) >> 5;
    int lane = threadIdx.x & 31;
    if (gw >= N_NODES) return;

    float adi = g_adst[gw];
    float asi = g_asrc[gw];

    // self loop term
    float a0 = asi + adi;
    a0 = a0 > 0.f ? a0 : 0.2f * a0;
    float w0 = __expf(a0);

    float4 v   = ((const float4*)(g_xp + (size_t)gw * OUT_CH))[lane];
    float4 acc = make_float4(w0 * v.x, w0 * v.y, w0 * v.z, w0 * v.w);
    float denom_l = 0.f;

    int beg = g_start[gw];
    int cnt = g_count[gw];

    for (int base = 0; base < cnt; base += 32) {
        int e = base + lane;
        int s = 0;
        float w = 0.f;
        if (e < cnt) {
            s = g_csr[beg + e];
            float a = g_asrc[s] + adi;
            a = a > 0.f ? a : 0.2f * a;
            w = __expf(a);
        }
        denom_l += w;
        int nv = cnt - base;
        if (nv > 32) nv = 32;
        for (int j = 0; j < nv; j++) {
            int   sj = __shfl_sync(FULL_MASK, s, j);
            float wj = __shfl_sync(FULL_MASK, w, j);
            float4 u = ((const float4*)(g_xp + (size_t)sj * OUT_CH))[lane];
            acc.x += wj * u.x;
            acc.y += wj * u.y;
            acc.z += wj * u.z;
            acc.w += wj * u.w;
        }
    }

#pragma unroll
    for (int off = 16; off; off >>= 1)
        denom_l += __shfl_xor_sync(FULL_MASK, denom_l, off);

    float inv = 1.f / (w0 + denom_l + 1e-16f);
    float4 b4 = ((const float4*)bias)[lane];
    float4 o  = make_float4(acc.x * inv + b4.x, acc.y * inv + b4.y,
                            acc.z * inv + b4.z, acc.w * inv + b4.w);
    ((float4*)(out + (size_t)gw * OUT_CH))[lane] = o;
}

// ---------------- launch ----------------
extern "C" void kernel_launch(void* const* d_in, const int* in_sizes, int n_in,
                              void* d_out, int out_size) {
    const float* x       = (const float*)d_in[0];
    const int*   ei      = (const int*)d_in[1];
    const float* W       = (const float*)d_in[2];
    const float* att_src = (const float*)d_in[3];
    const float* att_dst = (const float*)d_in[4];
    const float* bias    = (const float*)d_in[5];
    float*       out     = (float*)d_out;

    (void)in_sizes; (void)n_in; (void)out_size;

    init_kernel<<<(N_NODES + 1023) / 1024, 1024>>>();
    gemm_kernel<<<(N_NODES + 127) / 128, 256>>>(x, W);
    alpha_kernel<<<(N_NODES * 32 + 255) / 256, 256>>>(att_src, att_dst);
    hist_kernel<<<(N_EDGES + 255) / 256, 256>>>(ei);
    scan_kernel<<<(N_NODES + 1023) / 1024, 1024>>>();
    scatter_kernel<<<(N_EDGES + 255) / 256, 256>>>(ei);
    aggregate_kernel<<<(N_NODES * 32 + 255) / 256, 256>>>(bias, out);
}

// round 4
// speedup vs baseline: 1.5529x; 1.5529x over previous
#include <cuda_runtime.h>
#include <cstdint>

#define N_NODES 100000
#define IN_CH   256
#define OUT_CH  128
#define N_EDGES 1600000
#define FULL_MASK 0xFFFFFFFFu

// ---------------- scratch ----------------
__device__ __align__(16) float g_xp[(size_t)N_NODES * OUT_CH];
__device__ float g_asrc[N_NODES];
__device__ float g_adst[N_NODES];
__device__ int   g_count[N_NODES];
__device__ int   g_start[N_NODES];
__device__ int   g_cursor[N_NODES];
__device__ int   g_csr[N_EDGES];
__device__ int   g_base;

// ---------------- helpers ----------------
__device__ __forceinline__ uint32_t f2tf32(float v) {
    uint32_t t;
    asm("cvt.rna.tf32.f32 %0, %1;" : "=r"(t) : "f"(v));
    return t;
}
__device__ __forceinline__ void mma_tf32(float* c, const uint32_t* a, const uint32_t* b) {
    asm volatile(
        "mma.sync.aligned.m16n8k8.row.col.f32.tf32.tf32.f32 "
        "{%0,%1,%2,%3}, {%4,%5,%6,%7}, {%8,%9}, {%0,%1,%2,%3};"
        : "+f"(c[0]), "+f"(c[1]), "+f"(c[2]), "+f"(c[3])
        : "r"(a[0]), "r"(a[1]), "r"(a[2]), "r"(a[3]), "r"(b[0]), "r"(b[1]));
}

// ---------------- init ----------------
__global__ void init_kernel() {
    int i = blockIdx.x * blockDim.x + threadIdx.x;
    if (i < N_NODES) g_count[i] = 0;
    if (i == 0) g_base = 0;
}

// ---------------- GEMM (tf32 mma.sync) + fused alpha epilogue ----------------
// 128x128 CTA tile, 8 warps in 2(M)x4(N), warp tile 64x32, BK=32.
__global__ void __launch_bounds__(256) gemm_kernel(const float* __restrict__ X,
                                                   const float* __restrict__ W,
                                                   const float* __restrict__ att_src,
                                                   const float* __restrict__ att_dst) {
    __shared__ float As[128][40];    // [m][k], padded (40 words: 16B-aligned rows)
    __shared__ float Bs[32][132];    // [k][n], padded to break quad conflicts

    const int tid    = threadIdx.x;
    const int lane   = tid & 31;
    const int w      = tid >> 5;
    const int warp_m = w & 1;        // 0..1
    const int warp_n = w >> 1;       // 0..3
    const int gid    = lane >> 2;    // group id (row within tile)
    const int tig    = lane & 3;     // thread in group (k / col pair)
    const int bm     = blockIdx.x * 128;

    float acc[4][4][4];
#pragma unroll
    for (int mi = 0; mi < 4; mi++)
#pragma unroll
        for (int nj = 0; nj < 4; nj++)
#pragma unroll
            for (int q = 0; q < 4; q++) acc[mi][nj][q] = 0.f;

    for (int kc = 0; kc < 8; kc++) {
        const int k0 = kc * 32;
        // A tile: 128 rows x 32 k  (1024 float4 / 4 per thread), tf32-rounded
#pragma unroll
        for (int t = 0; t < 4; t++) {
            int idx = tid + t * 256;
            int row = idx >> 3;
            int kq  = (idx & 7) << 2;
            float4 v = make_float4(0.f, 0.f, 0.f, 0.f);
            if (bm + row < N_NODES)
                v = *(const float4*)&X[(size_t)(bm + row) * IN_CH + k0 + kq];
            float4 cv = make_float4(__uint_as_float(f2tf32(v.x)), __uint_as_float(f2tf32(v.y)),
                                    __uint_as_float(f2tf32(v.z)), __uint_as_float(f2tf32(v.w)));
            *(float4*)&As[row][kq] = cv;
        }
        // B tile: 32 k x 128 n from W (row-major [K][N]), tf32-rounded
#pragma unroll
        for (int t = 0; t < 4; t++) {
            int idx = tid + t * 256;
            int row = idx >> 5;
            int c   = (idx & 31) << 2;
            float4 v = *(const float4*)&W[(size_t)(k0 + row) * OUT_CH + c];
            float4 cv = make_float4(__uint_as_float(f2tf32(v.x)), __uint_as_float(f2tf32(v.y)),
                                    __uint_as_float(f2tf32(v.z)), __uint_as_float(f2tf32(v.w)));
            *(float4*)&Bs[row][c] = cv;
        }
        __syncthreads();

#pragma unroll
        for (int ks = 0; ks < 4; ks++) {
            const int kk = ks * 8;
            uint32_t a[4][4], b[4][2];
#pragma unroll
            for (int mi = 0; mi < 4; mi++) {
                int r = warp_m * 64 + mi * 16 + gid;
                a[mi][0] = __float_as_uint(As[r][kk + tig]);
                a[mi][1] = __float_as_uint(As[r + 8][kk + tig]);
                a[mi][2] = __float_as_uint(As[r][kk + tig + 4]);
                a[mi][3] = __float_as_uint(As[r + 8][kk + tig + 4]);
            }
#pragma unroll
            for (int nj = 0; nj < 4; nj++) {
                int cn = warp_n * 32 + nj * 8 + gid;
                b[nj][0] = __float_as_uint(Bs[kk + tig][cn]);
                b[nj][1] = __float_as_uint(Bs[kk + tig + 4][cn]);
            }
#pragma unroll
            for (int mi = 0; mi < 4; mi++)
#pragma unroll
                for (int nj = 0; nj < 4; nj++)
                    mma_tf32(acc[mi][nj], a[mi], b[nj]);
        }
        __syncthreads();
    }

    // ---- epilogue: store xp + fused alpha logits ----
    // column attention coefficients for this thread's column pairs
    float asv[4][2], adv[4][2];
#pragma unroll
    for (int nj = 0; nj < 4; nj++) {
        int c = warp_n * 32 + nj * 8 + 2 * tig;
        asv[nj][0] = __ldg(&att_src[c]);
        asv[nj][1] = __ldg(&att_src[c + 1]);
        adv[nj][0] = __ldg(&att_dst[c]);
        adv[nj][1] = __ldg(&att_dst[c + 1]);
    }

#pragma unroll
    for (int mi = 0; mi < 4; mi++) {
        int r0 = bm + warp_m * 64 + mi * 16 + gid;
        int r1 = r0 + 8;
        float ps0 = 0.f, pd0 = 0.f, ps1 = 0.f, pd1 = 0.f;
#pragma unroll
        for (int nj = 0; nj < 4; nj++) {
            int c = warp_n * 32 + nj * 8 + 2 * tig;
            float2 v0 = make_float2(acc[mi][nj][0], acc[mi][nj][1]);
            float2 v1 = make_float2(acc[mi][nj][2], acc[mi][nj][3]);
            if (r0 < N_NODES) *(float2*)&g_xp[(size_t)r0 * OUT_CH + c] = v0;
            if (r1 < N_NODES) *(float2*)&g_xp[(size_t)r1 * OUT_CH + c] = v1;
            ps0 += v0.x * asv[nj][0] + v0.y * asv[nj][1];
            pd0 += v0.x * adv[nj][0] + v0.y * adv[nj][1];
            ps1 += v1.x * asv[nj][0] + v1.y * asv[nj][1];
            pd1 += v1.x * adv[nj][0] + v1.y * adv[nj][1];
        }
        // quad reduction over tig (lanes differ only in low 2 bits)
#pragma unroll
        for (int off = 1; off < 4; off <<= 1) {
            ps0 += __shfl_xor_sync(FULL_MASK, ps0, off);
            pd0 += __shfl_xor_sync(FULL_MASK, pd0, off);
            ps1 += __shfl_xor_sync(FULL_MASK, ps1, off);
            pd1 += __shfl_xor_sync(FULL_MASK, pd1, off);
        }
        if (tig == 0 && warp_n == 0) {   // one warp column writes per row
            if (r0 < N_NODES) { /* partial: only warp_n 0's cols */ }
        }
        // NOTE: each warp_n column computed partial sums over its 32 cols only;
        // need cross-warp reduction -> use atomics-free split: store partials
        // per warp_n then sum? Simpler: atomicAdd into g_asrc/g_adst.
        if (tig == 0) {
            if (r0 < N_NODES) {
                atomicAdd(&g_asrc[r0], ps0);
                atomicAdd(&g_adst[r0], pd0);
            }
            if (r1 < N_NODES) {
                atomicAdd(&g_asrc[r1], ps1);
                atomicAdd(&g_adst[r1], pd1);
            }
        }
    }
}

// zero alpha accumulators (needed because epilogue uses atomicAdd)
__global__ void zero_alpha_kernel() {
    int i = blockIdx.x * blockDim.x + threadIdx.x;
    if (i < N_NODES) {
        g_asrc[i] = 0.f;
        g_adst[i] = 0.f;
    }
}

// ---------------- histogram over dst (drop self-edges), 4 edges/thread ----------------
__global__ void hist_kernel(const int* __restrict__ ei) {
    int t = blockIdx.x * blockDim.x + threadIdx.x;
    if (t >= N_EDGES / 4) return;
    int4 s = ((const int4*)ei)[t];
    int4 d = ((const int4*)(ei + N_EDGES))[t];
    if (s.x != d.x) atomicAdd(&g_count[d.x], 1);
    if (s.y != d.y) atomicAdd(&g_count[d.y], 1);
    if (s.z != d.z) atomicAdd(&g_count[d.z], 1);
    if (s.w != d.w) atomicAdd(&g_count[d.w], 1);
}

// ---------------- scan ----------------
__global__ void scan_kernel() {
    __shared__ int sh[1024];
    __shared__ int sbase;
    int i = blockIdx.x * 1024 + threadIdx.x;
    int c = (i < N_NODES) ? g_count[i] : 0;
    sh[threadIdx.x] = c;
    __syncthreads();
#pragma unroll
    for (int off = 1; off < 1024; off <<= 1) {
        int v = 0;
        if ((int)threadIdx.x >= off) v = sh[threadIdx.x - off];
        __syncthreads();
        sh[threadIdx.x] += v;
        __syncthreads();
    }
    if (threadIdx.x == 1023) sbase = atomicAdd(&g_base, sh[1023]);
    __syncthreads();
    if (i < N_NODES) {
        int st = sbase + sh[threadIdx.x] - c;
        g_start[i]  = st;
        g_cursor[i] = st;
    }
}

// ---------------- scatter into CSR, 4 edges/thread ----------------
__global__ void scatter_kernel(const int* __restrict__ ei) {
    int t = blockIdx.x * blockDim.x + threadIdx.x;
    if (t >= N_EDGES / 4) return;
    int4 s = ((const int4*)ei)[t];
    int4 d = ((const int4*)(ei + N_EDGES))[t];
    if (s.x != d.x) g_csr[atomicAdd(&g_cursor[d.x], 1)] = s.x;
    if (s.y != d.y) g_csr[atomicAdd(&g_cursor[d.y], 1)] = s.y;
    if (s.z != d.z) g_csr[atomicAdd(&g_cursor[d.z], 1)] = s.z;
    if (s.w != d.w) g_csr[atomicAdd(&g_cursor[d.w], 1)] = s.w;
}

// ---------------- fused softmax + weighted aggregation: one warp per dst ----------------
__global__ void __launch_bounds__(256) aggregate_kernel(const float* __restrict__ bias,
                                                        float* __restrict__ out) {
    int gw   = (blockIdx.x * blockDim.x + threadIdx.x) >> 5;
    int lane = threadIdx.x & 31;
    if (gw >= N_NODES) return;

    float adi = g_adst[gw];
    float asi = g_asrc[gw];

    float a0 = asi + adi;
    a0 = a0 > 0.f ? a0 : 0.2f * a0;
    float w0 = __expf(a0);

    float4 v   = ((const float4*)(g_xp + (size_t)gw * OUT_CH))[lane];
    float4 acc = make_float4(w0 * v.x, w0 * v.y, w0 * v.z, w0 * v.w);
    float denom_l = 0.f;

    int beg = g_start[gw];
    int cnt = g_count[gw];

    for (int base = 0; base < cnt; base += 32) {
        int e = base + lane;
        int s = 0;
        float w = 0.f;
        if (e < cnt) {
            s = g_csr[beg + e];
            float a = g_asrc[s] + adi;
            a = a > 0.f ? a : 0.2f * a;
            w = __expf(a);
        }
        denom_l += w;
        int nv = cnt - base;
        if (nv > 32) nv = 32;
        for (int j = 0; j < nv; j++) {
            int   sj = __shfl_sync(FULL_MASK, s, j);
            float wj = __shfl_sync(FULL_MASK, w, j);
            float4 u = ((const float4*)(g_xp + (size_t)sj * OUT_CH))[lane];
            acc.x += wj * u.x;
            acc.y += wj * u.y;
            acc.z += wj * u.z;
            acc.w += wj * u.w;
        }
    }

#pragma unroll
    for (int off = 16; off; off >>= 1)
        denom_l += __shfl_xor_sync(FULL_MASK, denom_l, off);

    float inv = 1.f / (w0 + denom_l + 1e-16f);
    float4 b4 = ((const float4*)bias)[lane];
    float4 o  = make_float4(acc.x * inv + b4.x, acc.y * inv + b4.y,
                            acc.z * inv + b4.z, acc.w * inv + b4.w);
    ((float4*)(out + (size_t)gw * OUT_CH))[lane] = o;
}

// ---------------- launch ----------------
extern "C" void kernel_launch(void* const* d_in, const int* in_sizes, int n_in,
                              void* d_out, int out_size) {
    const float* x       = (const float*)d_in[0];
    const int*   ei      = (const int*)d_in[1];
    const float* W       = (const float*)d_in[2];
    const float* att_src = (const float*)d_in[3];
    const float* att_dst = (const float*)d_in[4];
    const float* bias    = (const float*)d_in[5];
    float*       out     = (float*)d_out;

    (void)in_sizes; (void)n_in; (void)out_size;

    init_kernel<<<(N_NODES + 1023) / 1024, 1024>>>();
    zero_alpha_kernel<<<(N_NODES + 1023) / 1024, 1024>>>();
    gemm_kernel<<<(N_NODES + 127) / 128, 256>>>(x, W, att_src, att_dst);
    hist_kernel<<<(N_EDGES / 4 + 255) / 256, 256>>>(ei);
    scan_kernel<<<(N_NODES + 1023) / 1024, 1024>>>();
    scatter_kernel<<<(N_EDGES / 4 + 255) / 256, 256>>>(ei);
    aggregate_kernel<<<(N_NODES * 32 + 255) / 256, 256>>>(bias, out);
}

// round 5
// speedup vs baseline: 1.6973x; 1.0930x over previous
#include <cuda_runtime.h>
#include <cstdint>

#define N_NODES 100000
#define IN_CH   256
#define OUT_CH  128
#define N_EDGES 1600000
#define FULL_MASK 0xFFFFFFFFu

// ---------------- scratch ----------------
__device__ __align__(16) float g_xp[(size_t)N_NODES * OUT_CH];
__device__ float g_asrc[N_NODES];
__device__ float g_adst[N_NODES];
__device__ int   g_count[N_NODES];
__device__ int   g_start[N_NODES];
__device__ int   g_cursor[N_NODES];
__device__ int   g_csr[N_EDGES];
__device__ int   g_base;

// ---------------- helpers ----------------
__device__ __forceinline__ uint32_t f2tf32(float v) {
    uint32_t t;
    asm("cvt.rna.tf32.f32 %0, %1;" : "=r"(t) : "f"(v));
    return t;
}
__device__ __forceinline__ void mma_tf32(float* c, const uint32_t* a, const uint32_t* b) {
    asm volatile(
        "mma.sync.aligned.m16n8k8.row.col.f32.tf32.tf32.f32 "
        "{%0,%1,%2,%3}, {%4,%5,%6,%7}, {%8,%9}, {%0,%1,%2,%3};"
        : "+f"(c[0]), "+f"(c[1]), "+f"(c[2]), "+f"(c[3])
        : "r"(a[0]), "r"(a[1]), "r"(a[2]), "r"(a[3]), "r"(b[0]), "r"(b[1]));
}

// ---------------- init: zero histogram + base ----------------
__global__ void init_kernel() {
    int i = blockIdx.x * blockDim.x + threadIdx.x;
    if (i < N_NODES) g_count[i] = 0;
    if (i == 0) g_base = 0;
}

// ---------------- GEMM (tf32 mma.sync) + fused alpha epilogue (smem reduce) ----------------
// 128x128 CTA tile, 8 warps in 2(M)x4(N), warp tile 64x32, BK=32.
__global__ void __launch_bounds__(256) gemm_kernel(const float* __restrict__ X,
                                                   const float* __restrict__ W,
                                                   const float* __restrict__ att_src,
                                                   const float* __restrict__ att_dst) {
    __shared__ float As[128][40];    // [m][k], padded
    __shared__ float Bs[32][132];    // [k][n], padded
    __shared__ float s_a[256];       // [row][0]=ps, [row][1]=pd interleaved: s_a[row*2+sel]

    const int tid    = threadIdx.x;
    const int lane   = tid & 31;
    const int w      = tid >> 5;
    const int warp_m = w & 1;
    const int warp_n = w >> 1;
    const int gid    = lane >> 2;
    const int tig    = lane & 3;
    const int bm     = blockIdx.x * 128;

    float acc[4][4][4];
#pragma unroll
    for (int mi = 0; mi < 4; mi++)
#pragma unroll
        for (int nj = 0; nj < 4; nj++)
#pragma unroll
            for (int q = 0; q < 4; q++) acc[mi][nj][q] = 0.f;

    for (int kc = 0; kc < 8; kc++) {
        const int k0 = kc * 32;
#pragma unroll
        for (int t = 0; t < 4; t++) {
            int idx = tid + t * 256;
            int row = idx >> 3;
            int kq  = (idx & 7) << 2;
            float4 v = make_float4(0.f, 0.f, 0.f, 0.f);
            if (bm + row < N_NODES)
                v = *(const float4*)&X[(size_t)(bm + row) * IN_CH + k0 + kq];
            float4 cv = make_float4(__uint_as_float(f2tf32(v.x)), __uint_as_float(f2tf32(v.y)),
                                    __uint_as_float(f2tf32(v.z)), __uint_as_float(f2tf32(v.w)));
            *(float4*)&As[row][kq] = cv;
        }
#pragma unroll
        for (int t = 0; t < 4; t++) {
            int idx = tid + t * 256;
            int row = idx >> 5;
            int c   = (idx & 31) << 2;
            float4 v = *(const float4*)&W[(size_t)(k0 + row) * OUT_CH + c];
            float4 cv = make_float4(__uint_as_float(f2tf32(v.x)), __uint_as_float(f2tf32(v.y)),
                                    __uint_as_float(f2tf32(v.z)), __uint_as_float(f2tf32(v.w)));
            *(float4*)&Bs[row][c] = cv;
        }
        __syncthreads();

#pragma unroll
        for (int ks = 0; ks < 4; ks++) {
            const int kk = ks * 8;
            uint32_t a[4][4], b[4][2];
#pragma unroll
            for (int mi = 0; mi < 4; mi++) {
                int r = warp_m * 64 + mi * 16 + gid;
                a[mi][0] = __float_as_uint(As[r][kk + tig]);
                a[mi][1] = __float_as_uint(As[r + 8][kk + tig]);
                a[mi][2] = __float_as_uint(As[r][kk + tig + 4]);
                a[mi][3] = __float_as_uint(As[r + 8][kk + tig + 4]);
            }
#pragma unroll
            for (int nj = 0; nj < 4; nj++) {
                int cn = warp_n * 32 + nj * 8 + gid;
                b[nj][0] = __float_as_uint(Bs[kk + tig][cn]);
                b[nj][1] = __float_as_uint(Bs[kk + tig + 4][cn]);
            }
#pragma unroll
            for (int mi = 0; mi < 4; mi++)
#pragma unroll
                for (int nj = 0; nj < 4; nj++)
                    mma_tf32(acc[mi][nj], a[mi], b[nj]);
        }
        __syncthreads();
    }

    // ---- epilogue: store xp + alpha logits via smem reduction ----
    s_a[tid] = 0.f;
    __syncthreads();

    float asv[4][2], adv[4][2];
#pragma unroll
    for (int nj = 0; nj < 4; nj++) {
        int c = warp_n * 32 + nj * 8 + 2 * tig;
        asv[nj][0] = __ldg(&att_src[c]);
        asv[nj][1] = __ldg(&att_src[c + 1]);
        adv[nj][0] = __ldg(&att_dst[c]);
        adv[nj][1] = __ldg(&att_dst[c + 1]);
    }

#pragma unroll
    for (int mi = 0; mi < 4; mi++) {
        int lr0 = warp_m * 64 + mi * 16 + gid;   // local row 0..127
        int lr1 = lr0 + 8;
        int r0 = bm + lr0;
        int r1 = bm + lr1;
        float ps0 = 0.f, pd0 = 0.f, ps1 = 0.f, pd1 = 0.f;
#pragma unroll
        for (int nj = 0; nj < 4; nj++) {
            int c = warp_n * 32 + nj * 8 + 2 * tig;
            float2 v0 = make_float2(acc[mi][nj][0], acc[mi][nj][1]);
            float2 v1 = make_float2(acc[mi][nj][2], acc[mi][nj][3]);
            if (r0 < N_NODES) *(float2*)&g_xp[(size_t)r0 * OUT_CH + c] = v0;
            if (r1 < N_NODES) *(float2*)&g_xp[(size_t)r1 * OUT_CH + c] = v1;
            ps0 += v0.x * asv[nj][0] + v0.y * asv[nj][1];
            pd0 += v0.x * adv[nj][0] + v0.y * adv[nj][1];
            ps1 += v1.x * asv[nj][0] + v1.y * asv[nj][1];
            pd1 += v1.x * adv[nj][0] + v1.y * adv[nj][1];
        }
#pragma unroll
        for (int off = 1; off < 4; off <<= 1) {
            ps0 += __shfl_xor_sync(FULL_MASK, ps0, off);
            pd0 += __shfl_xor_sync(FULL_MASK, pd0, off);
            ps1 += __shfl_xor_sync(FULL_MASK, ps1, off);
            pd1 += __shfl_xor_sync(FULL_MASK, pd1, off);
        }
        if (tig == 0) {
            atomicAdd(&s_a[lr0 * 2 + 0], ps0);
            atomicAdd(&s_a[lr0 * 2 + 1], pd0);
            atomicAdd(&s_a[lr1 * 2 + 0], ps1);
            atomicAdd(&s_a[lr1 * 2 + 1], pd1);
        }
    }
    __syncthreads();

    if (tid < 128) {
        int r = bm + tid;
        if (r < N_NODES) {
            g_asrc[r] = s_a[tid * 2 + 0];
            g_adst[r] = s_a[tid * 2 + 1];
        }
    }
}

// ---------------- histogram over dst (drop self-edges), 4 edges/thread ----------------
__global__ void hist_kernel(const int* __restrict__ ei) {
    int t = blockIdx.x * blockDim.x + threadIdx.x;
    if (t >= N_EDGES / 4) return;
    int4 s = ((const int4*)ei)[t];
    int4 d = ((const int4*)(ei + N_EDGES))[t];
    if (s.x != d.x) atomicAdd(&g_count[d.x], 1);
    if (s.y != d.y) atomicAdd(&g_count[d.y], 1);
    if (s.z != d.z) atomicAdd(&g_count[d.z], 1);
    if (s.w != d.w) atomicAdd(&g_count[d.w], 1);
}

// ---------------- scan ----------------
__global__ void scan_kernel() {
    __shared__ int sh[1024];
    __shared__ int sbase;
    int i = blockIdx.x * 1024 + threadIdx.x;
    int c = (i < N_NODES) ? g_count[i] : 0;
    sh[threadIdx.x] = c;
    __syncthreads();
#pragma unroll
    for (int off = 1; off < 1024; off <<= 1) {
        int v = 0;
        if ((int)threadIdx.x >= off) v = sh[threadIdx.x - off];
        __syncthreads();
        sh[threadIdx.x] += v;
        __syncthreads();
    }
    if (threadIdx.x == 1023) sbase = atomicAdd(&g_base, sh[1023]);
    __syncthreads();
    if (i < N_NODES) {
        int st = sbase + sh[threadIdx.x] - c;
        g_start[i]  = st;
        g_cursor[i] = st;
    }
}

// ---------------- scatter into CSR, 4 edges/thread ----------------
__global__ void scatter_kernel(const int* __restrict__ ei) {
    int t = blockIdx.x * blockDim.x + threadIdx.x;
    if (t >= N_EDGES / 4) return;
    int4 s = ((const int4*)ei)[t];
    int4 d = ((const int4*)(ei + N_EDGES))[t];
    if (s.x != d.x) g_csr[atomicAdd(&g_cursor[d.x], 1)] = s.x;
    if (s.y != d.y) g_csr[atomicAdd(&g_cursor[d.y], 1)] = s.y;
    if (s.z != d.z) g_csr[atomicAdd(&g_cursor[d.z], 1)] = s.z;
    if (s.w != d.w) g_csr[atomicAdd(&g_cursor[d.w], 1)] = s.w;
}

// ---------------- fused softmax + weighted aggregation: one warp per dst ----------------
__global__ void __launch_bounds__(256) aggregate_kernel(const float* __restrict__ bias,
                                                        float* __restrict__ out) {
    int gw   = (blockIdx.x * blockDim.x + threadIdx.x) >> 5;
    int lane = threadIdx.x & 31;
    if (gw >= N_NODES) return;

    float adi = g_adst[gw];
    float asi = g_asrc[gw];

    float a0 = asi + adi;
    a0 = a0 > 0.f ? a0 : 0.2f * a0;
    float w0 = __expf(a0);

    float4 v   = ((const float4*)(g_xp + (size_t)gw * OUT_CH))[lane];
    float4 acc = make_float4(w0 * v.x, w0 * v.y, w0 * v.z, w0 * v.w);
    float denom_l = 0.f;

    int beg = g_start[gw];
    int cnt = g_count[gw];

    for (int base = 0; base < cnt; base += 32) {
        int e = base + lane;
        int s = 0;
        float w = 0.f;
        if (e < cnt) {
            s = g_csr[beg + e];
            float a = g_asrc[s] + adi;
            a = a > 0.f ? a : 0.2f * a;
            w = __expf(a);
        }
        denom_l += w;
        int nv = cnt - base;
        if (nv > 32) nv = 32;
        for (int j = 0; j < nv; j++) {
            int   sj = __shfl_sync(FULL_MASK, s, j);
            float wj = __shfl_sync(FULL_MASK, w, j);
            float4 u = ((const float4*)(g_xp + (size_t)sj * OUT_CH))[lane];
            acc.x += wj * u.x;
            acc.y += wj * u.y;
            acc.z += wj * u.z;
            acc.w += wj * u.w;
        }
    }

#pragma unroll
    for (int off = 16; off; off >>= 1)
        denom_l += __shfl_xor_sync(FULL_MASK, denom_l, off);

    float inv = 1.f / (w0 + denom_l + 1e-16f);
    float4 b4 = ((const float4*)bias)[lane];
    float4 o  = make_float4(acc.x * inv + b4.x, acc.y * inv + b4.y,
                            acc.z * inv + b4.z, acc.w * inv + b4.w);
    ((float4*)(out + (size_t)gw * OUT_CH))[lane] = o;
}

// ---------------- launch: fork/join graph parallelism ----------------
extern "C" void kernel_launch(void* const* d_in, const int* in_sizes, int n_in,
                              void* d_out, int out_size) {
    const float* x       = (const float*)d_in[0];
    const int*   ei      = (const int*)d_in[1];
    const float* W       = (const float*)d_in[2];
    const float* att_src = (const float*)d_in[3];
    const float* att_dst = (const float*)d_in[4];
    const float* bias    = (const float*)d_in[5];
    float*       out     = (float*)d_out;

    (void)in_sizes; (void)n_in; (void)out_size;

    static cudaStream_t sA = nullptr, sB = nullptr;
    static cudaEvent_t  ev0 = nullptr, evA = nullptr, evB = nullptr;
    if (sA == nullptr) {
        cudaStreamCreateWithFlags(&sA, cudaStreamNonBlocking);
        cudaStreamCreateWithFlags(&sB, cudaStreamNonBlocking);
        cudaEventCreateWithFlags(&ev0, cudaEventDisableTiming);
        cudaEventCreateWithFlags(&evA, cudaEventDisableTiming);
        cudaEventCreateWithFlags(&evB, cudaEventDisableTiming);
    }

    // root work on the capture-origin (default) stream
    init_kernel<<<(N_NODES + 1023) / 1024, 1024>>>();

    // fork
    cudaEventRecord(ev0, 0);
    cudaStreamWaitEvent(sA, ev0, 0);
    cudaStreamWaitEvent(sB, ev0, 0);

    // branch A: GEMM + fused alpha
    gemm_kernel<<<(N_NODES + 127) / 128, 256, 0, sA>>>(x, W, att_src, att_dst);

    // branch B: CSR build
    hist_kernel<<<(N_EDGES / 4 + 255) / 256, 256, 0, sB>>>(ei);
    scan_kernel<<<(N_NODES + 1023) / 1024, 1024, 0, sB>>>();
    scatter_kernel<<<(N_EDGES / 4 + 255) / 256, 256, 0, sB>>>(ei);

    // join
    cudaEventRecord(evA, sA);
    cudaEventRecord(evB, sB);
    cudaStreamWaitEvent(0, evA, 0);
    cudaStreamWaitEvent(0, evB, 0);

    aggregate_kernel<<<(N_NODES * 32 + 255) / 256, 256>>>(bias, out);
}

// round 6
// speedup vs baseline: 1.7977x; 1.0592x over previous
#include <cuda_runtime.h>
#include <cuda_fp16.h>
#include <cstdint>

#define N_NODES 100000
#define IN_CH   256
#define OUT_CH  128
#define N_EDGES 1600000
#define FULL_MASK 0xFFFFFFFFu

// ---------------- scratch ----------------
__device__ __align__(16) float   g_xp[(size_t)N_NODES * OUT_CH];   // fp32 xp (self-loop path)
__device__ __align__(16) __half2 g_xph[(size_t)N_NODES * (OUT_CH / 2)]; // fp16 xp (gather path)
__device__ float g_asrc[N_NODES];
__device__ float g_adst[N_NODES];
__device__ int   g_count[N_NODES];
__device__ int   g_start[N_NODES];
__device__ int   g_cursor[N_NODES];
__device__ int   g_csr[N_EDGES];
__device__ int   g_base;

// ---------------- helpers ----------------
__device__ __forceinline__ uint32_t f2tf32(float v) {
    uint32_t t;
    asm("cvt.rna.tf32.f32 %0, %1;" : "=r"(t) : "f"(v));
    return t;
}
__device__ __forceinline__ void mma_tf32(float* c, const uint32_t* a, const uint32_t* b) {
    asm volatile(
        "mma.sync.aligned.m16n8k8.row.col.f32.tf32.tf32.f32 "
        "{%0,%1,%2,%3}, {%4,%5,%6,%7}, {%8,%9}, {%0,%1,%2,%3};"
        : "+f"(c[0]), "+f"(c[1]), "+f"(c[2]), "+f"(c[3])
        : "r"(a[0]), "r"(a[1]), "r"(a[2]), "r"(a[3]), "r"(b[0]), "r"(b[1]));
}

// ---------------- init: zero histogram + base ----------------
__global__ void init_kernel() {
    int i = blockIdx.x * blockDim.x + threadIdx.x;
    if (i < N_NODES) g_count[i] = 0;
    if (i == 0) g_base = 0;
}

// ---------------- GEMM (tf32 mma.sync) + fused alpha + fp16 emit ----------------
// 128x128 CTA tile, 8 warps in 2(M)x4(N), warp tile 64x32, BK=32.
__global__ void __launch_bounds__(256) gemm_kernel(const float* __restrict__ X,
                                                   const float* __restrict__ W,
                                                   const float* __restrict__ att_src,
                                                   const float* __restrict__ att_dst) {
    __shared__ float As[128][40];
    __shared__ float Bs[32][132];
    __shared__ float s_a[256];   // s_a[row*2+0]=ps, +1=pd

    const int tid    = threadIdx.x;
    const int lane   = tid & 31;
    const int w      = tid >> 5;
    const int warp_m = w & 1;
    const int warp_n = w >> 1;
    const int gid    = lane >> 2;
    const int tig    = lane & 3;
    const int bm     = blockIdx.x * 128;

    float acc[4][4][4];
#pragma unroll
    for (int mi = 0; mi < 4; mi++)
#pragma unroll
        for (int nj = 0; nj < 4; nj++)
#pragma unroll
            for (int q = 0; q < 4; q++) acc[mi][nj][q] = 0.f;

    for (int kc = 0; kc < 8; kc++) {
        const int k0 = kc * 32;
#pragma unroll
        for (int t = 0; t < 4; t++) {
            int idx = tid + t * 256;
            int row = idx >> 3;
            int kq  = (idx & 7) << 2;
            float4 v = make_float4(0.f, 0.f, 0.f, 0.f);
            if (bm + row < N_NODES)
                v = *(const float4*)&X[(size_t)(bm + row) * IN_CH + k0 + kq];
            float4 cv = make_float4(__uint_as_float(f2tf32(v.x)), __uint_as_float(f2tf32(v.y)),
                                    __uint_as_float(f2tf32(v.z)), __uint_as_float(f2tf32(v.w)));
            *(float4*)&As[row][kq] = cv;
        }
#pragma unroll
        for (int t = 0; t < 4; t++) {
            int idx = tid + t * 256;
            int row = idx >> 5;
            int c   = (idx & 31) << 2;
            float4 v = *(const float4*)&W[(size_t)(k0 + row) * OUT_CH + c];
            float4 cv = make_float4(__uint_as_float(f2tf32(v.x)), __uint_as_float(f2tf32(v.y)),
                                    __uint_as_float(f2tf32(v.z)), __uint_as_float(f2tf32(v.w)));
            *(float4*)&Bs[row][c] = cv;
        }
        __syncthreads();

#pragma unroll
        for (int ks = 0; ks < 4; ks++) {
            const int kk = ks * 8;
            uint32_t a[4][4], b[4][2];
#pragma unroll
            for (int mi = 0; mi < 4; mi++) {
                int r = warp_m * 64 + mi * 16 + gid;
                a[mi][0] = __float_as_uint(As[r][kk + tig]);
                a[mi][1] = __float_as_uint(As[r + 8][kk + tig]);
                a[mi][2] = __float_as_uint(As[r][kk + tig + 4]);
                a[mi][3] = __float_as_uint(As[r + 8][kk + tig + 4]);
            }
#pragma unroll
            for (int nj = 0; nj < 4; nj++) {
                int cn = warp_n * 32 + nj * 8 + gid;
                b[nj][0] = __float_as_uint(Bs[kk + tig][cn]);
                b[nj][1] = __float_as_uint(Bs[kk + tig + 4][cn]);
            }
#pragma unroll
            for (int mi = 0; mi < 4; mi++)
#pragma unroll
                for (int nj = 0; nj < 4; nj++)
                    mma_tf32(acc[mi][nj], a[mi], b[nj]);
        }
        __syncthreads();
    }

    // ---- epilogue ----
    s_a[tid] = 0.f;
    __syncthreads();

    float asv[4][2], adv[4][2];
#pragma unroll
    for (int nj = 0; nj < 4; nj++) {
        int c = warp_n * 32 + nj * 8 + 2 * tig;
        asv[nj][0] = __ldg(&att_src[c]);
        asv[nj][1] = __ldg(&att_src[c + 1]);
        adv[nj][0] = __ldg(&att_dst[c]);
        adv[nj][1] = __ldg(&att_dst[c + 1]);
    }

#pragma unroll
    for (int mi = 0; mi < 4; mi++) {
        int lr0 = warp_m * 64 + mi * 16 + gid;
        int lr1 = lr0 + 8;
        int r0 = bm + lr0;
        int r1 = bm + lr1;
        float ps0 = 0.f, pd0 = 0.f, ps1 = 0.f, pd1 = 0.f;
#pragma unroll
        for (int nj = 0; nj < 4; nj++) {
            int c  = warp_n * 32 + nj * 8 + 2 * tig;
            int hc = c >> 1;   // half2 index within row
            float2 v0 = make_float2(acc[mi][nj][0], acc[mi][nj][1]);
            float2 v1 = make_float2(acc[mi][nj][2], acc[mi][nj][3]);
            if (r0 < N_NODES) {
                *(float2*)&g_xp[(size_t)r0 * OUT_CH + c] = v0;
                g_xph[(size_t)r0 * (OUT_CH / 2) + hc] = __floats2half2_rn(v0.x, v0.y);
            }
            if (r1 < N_NODES) {
                *(float2*)&g_xp[(size_t)r1 * OUT_CH + c] = v1;
                g_xph[(size_t)r1 * (OUT_CH / 2) + hc] = __floats2half2_rn(v1.x, v1.y);
            }
            ps0 += v0.x * asv[nj][0] + v0.y * asv[nj][1];
            pd0 += v0.x * adv[nj][0] + v0.y * adv[nj][1];
            ps1 += v1.x * asv[nj][0] + v1.y * asv[nj][1];
            pd1 += v1.x * adv[nj][0] + v1.y * adv[nj][1];
        }
#pragma unroll
        for (int off = 1; off < 4; off <<= 1) {
            ps0 += __shfl_xor_sync(FULL_MASK, ps0, off);
            pd0 += __shfl_xor_sync(FULL_MASK, pd0, off);
            ps1 += __shfl_xor_sync(FULL_MASK, ps1, off);
            pd1 += __shfl_xor_sync(FULL_MASK, pd1, off);
        }
        if (tig == 0) {
            atomicAdd(&s_a[lr0 * 2 + 0], ps0);
            atomicAdd(&s_a[lr0 * 2 + 1], pd0);
            atomicAdd(&s_a[lr1 * 2 + 0], ps1);
            atomicAdd(&s_a[lr1 * 2 + 1], pd1);
        }
    }
    __syncthreads();

    if (tid < 128) {
        int r = bm + tid;
        if (r < N_NODES) {
            g_asrc[r] = s_a[tid * 2 + 0];
            g_adst[r] = s_a[tid * 2 + 1];
        }
    }
}

// ---------------- histogram over dst (drop self-edges), 4 edges/thread ----------------
__global__ void hist_kernel(const int* __restrict__ ei) {
    int t = blockIdx.x * blockDim.x + threadIdx.x;
    if (t >= N_EDGES / 4) return;
    int4 s = ((const int4*)ei)[t];
    int4 d = ((const int4*)(ei + N_EDGES))[t];
    if (s.x != d.x) atomicAdd(&g_count[d.x], 1);
    if (s.y != d.y) atomicAdd(&g_count[d.y], 1);
    if (s.z != d.z) atomicAdd(&g_count[d.z], 1);
    if (s.w != d.w) atomicAdd(&g_count[d.w], 1);
}

// ---------------- scan (warp-shuffle) ----------------
__global__ void scan_kernel() {
    __shared__ int wsum[32];
    __shared__ int sbase;
    const int tid  = threadIdx.x;
    const int lane = tid & 31;
    const int wid  = tid >> 5;
    int i = blockIdx.x * 1024 + tid;
    int c = (i < N_NODES) ? g_count[i] : 0;

    // intra-warp inclusive scan
    int v = c;
#pragma unroll
    for (int off = 1; off < 32; off <<= 1) {
        int t = __shfl_up_sync(FULL_MASK, v, off);
        if (lane >= off) v += t;
    }
    if (lane == 31) wsum[wid] = v;
    __syncthreads();

    if (wid == 0) {
        int s = wsum[lane];
#pragma unroll
        for (int off = 1; off < 32; off <<= 1) {
            int t = __shfl_up_sync(FULL_MASK, s, off);
            if (lane >= off) s += t;
        }
        wsum[lane] = s;
        if (lane == 31) sbase = atomicAdd(&g_base, s);
    }
    __syncthreads();

    if (i < N_NODES) {
        int prefix = (wid > 0) ? wsum[wid - 1] : 0;
        int st = sbase + prefix + v - c;
        g_start[i]  = st;
        g_cursor[i] = st;
    }
}

// ---------------- scatter into CSR, 4 edges/thread ----------------
__global__ void scatter_kernel(const int* __restrict__ ei) {
    int t = blockIdx.x * blockDim.x + threadIdx.x;
    if (t >= N_EDGES / 4) return;
    int4 s = ((const int4*)ei)[t];
    int4 d = ((const int4*)(ei + N_EDGES))[t];
    if (s.x != d.x) g_csr[atomicAdd(&g_cursor[d.x], 1)] = s.x;
    if (s.y != d.y) g_csr[atomicAdd(&g_cursor[d.y], 1)] = s.y;
    if (s.z != d.z) g_csr[atomicAdd(&g_cursor[d.z], 1)] = s.z;
    if (s.w != d.w) g_csr[atomicAdd(&g_cursor[d.w], 1)] = s.w;
}

// ---------------- fused softmax + aggregation: one warp per dst, fp16 gather ----------------
__global__ void __launch_bounds__(256) aggregate_kernel(const float* __restrict__ bias,
                                                        float* __restrict__ out) {
    int gw   = (blockIdx.x * blockDim.x + threadIdx.x) >> 5;
    int lane = threadIdx.x & 31;
    if (gw >= N_NODES) return;

    float adi = g_adst[gw];
    float asi = g_asrc[gw];

    float a0 = asi + adi;
    a0 = a0 > 0.f ? a0 : 0.2f * a0;
    float w0 = __expf(a0);

    // self term from fp32 xp
    float4 v   = ((const float4*)(g_xp + (size_t)gw * OUT_CH))[lane];
    float4 acc = make_float4(w0 * v.x, w0 * v.y, w0 * v.z, w0 * v.w);
    float denom_l = 0.f;

    int beg = g_start[gw];
    int cnt = g_count[gw];

    const uint2* xph = (const uint2*)g_xph;   // 32 uint2 per row (4 halves each)

    for (int base = 0; base < cnt; base += 32) {
        int e = base + lane;
        int s = 0;
        float w = 0.f;
        if (e < cnt) {
            s = g_csr[beg + e];
            float a = g_asrc[s] + adi;
            a = a > 0.f ? a : 0.2f * a;
            w = __expf(a);
        }
        denom_l += w;
        int nv = cnt - base;
        if (nv > 32) nv = 32;
        for (int j = 0; j < nv; j++) {
            int   sj = __shfl_sync(FULL_MASK, s, j);
            float wj = __shfl_sync(FULL_MASK, w, j);
            uint2 h  = xph[(size_t)sj * 32 + lane];
            float2 p0 = __half22float2(*(const __half2*)&h.x);
            float2 p1 = __half22float2(*(const __half2*)&h.y);
            acc.x += wj * p0.x;
            acc.y += wj * p0.y;
            acc.z += wj * p1.x;
            acc.w += wj * p1.y;
        }
    }

#pragma unroll
    for (int off = 16; off; off >>= 1)
        denom_l += __shfl_xor_sync(FULL_MASK, denom_l, off);

    float inv = 1.f / (w0 + denom_l + 1e-16f);
    float4 b4 = ((const float4*)bias)[lane];
    float4 o  = make_float4(acc.x * inv + b4.x, acc.y * inv + b4.y,
                            acc.z * inv + b4.z, acc.w * inv + b4.w);
    ((float4*)(out + (size_t)gw * OUT_CH))[lane] = o;
}

// ---------------- launch: fork/join ----------------
extern "C" void kernel_launch(void* const* d_in, const int* in_sizes, int n_in,
                              void* d_out, int out_size) {
    const float* x       = (const float*)d_in[0];
    const int*   ei      = (const int*)d_in[1];
    const float* W       = (const float*)d_in[2];
    const float* att_src = (const float*)d_in[3];
    const float* att_dst = (const float*)d_in[4];
    const float* bias    = (const float*)d_in[5];
    float*       out     = (float*)d_out;

    (void)in_sizes; (void)n_in; (void)out_size;

    static cudaStream_t sA = nullptr, sB = nullptr;
    static cudaEvent_t  ev0 = nullptr, evA = nullptr, evB = nullptr;
    if (sA == nullptr) {
        cudaStreamCreateWithFlags(&sA, cudaStreamNonBlocking);
        cudaStreamCreateWithFlags(&sB, cudaStreamNonBlocking);
        cudaEventCreateWithFlags(&ev0, cudaEventDisableTiming);
        cudaEventCreateWithFlags(&evA, cudaEventDisableTiming);
        cudaEventCreateWithFlags(&evB, cudaEventDisableTiming);
    }

    // fork from origin stream
    cudaEventRecord(ev0, 0);
    cudaStreamWaitEvent(sA, ev0, 0);
    cudaStreamWaitEvent(sB, ev0, 0);

    // branch A: GEMM + fused alpha + fp16 emit
    gemm_kernel<<<(N_NODES + 127) / 128, 256, 0, sA>>>(x, W, att_src, att_dst);

    // branch B: CSR build (init moved here — GEMM no longer waits)
    init_kernel<<<(N_NODES + 1023) / 1024, 1024, 0, sB>>>();
    hist_kernel<<<(N_EDGES / 4 + 255) / 256, 256, 0, sB>>>(ei);
    scan_kernel<<<(N_NODES + 1023) / 1024, 1024, 0, sB>>>();
    scatter_kernel<<<(N_EDGES / 4 + 255) / 256, 256, 0, sB>>>(ei);

    // join
    cudaEventRecord(evA, sA);
    cudaEventRecord(evB, sB);
    cudaStreamWaitEvent(0, evA, 0);
    cudaStreamWaitEvent(0, evB, 0);

    aggregate_kernel<<<(N_NODES * 32 + 255) / 256, 256>>>(bias, out);
}

// round 7
// speedup vs baseline: 1.9844x; 1.1038x over previous
#include <cuda_runtime.h>
#include <cuda_fp16.h>
#include <cstdint>

#define N_NODES 100000
#define IN_CH   256
#define OUT_CH  128
#define N_EDGES 1600000
#define FULL_MASK 0xFFFFFFFFu

// ---------------- scratch ----------------
__device__ __align__(16) __half2 g_xph[(size_t)N_NODES * (OUT_CH / 2)]; // fp16 xp
__device__ float g_asrc[N_NODES];
__device__ float g_adst[N_NODES];
__device__ int   g_count[N_NODES];
__device__ int   g_start[N_NODES];
__device__ int   g_cursor[N_NODES];
__device__ int   g_csr[N_EDGES];
__device__ int   g_base;

// ---------------- helpers ----------------
__device__ __forceinline__ uint32_t f2tf32(float v) {
    uint32_t t;
    asm("cvt.rna.tf32.f32 %0, %1;" : "=r"(t) : "f"(v));
    return t;
}
__device__ __forceinline__ void mma_tf32(float* c, const uint32_t* a, const uint32_t* b) {
    asm volatile(
        "mma.sync.aligned.m16n8k8.row.col.f32.tf32.tf32.f32 "
        "{%0,%1,%2,%3}, {%4,%5,%6,%7}, {%8,%9}, {%0,%1,%2,%3};"
        : "+f"(c[0]), "+f"(c[1]), "+f"(c[2]), "+f"(c[3])
        : "r"(a[0]), "r"(a[1]), "r"(a[2]), "r"(a[3]), "r"(b[0]), "r"(b[1]));
}
__device__ __forceinline__ uint32_t smem_u32(const void* p) {
    uint32_t a;
    asm("{ .reg .u64 t; cvta.to.shared.u64 t, %1; cvt.u32.u64 %0, t; }" : "=r"(a) : "l"(p));
    return a;
}
__device__ __forceinline__ void cp16(uint32_t dst, const void* src, int bytes) {
    asm volatile("cp.async.cg.shared.global [%0], [%1], 16, %2;"
                 :: "r"(dst), "l"(src), "r"(bytes) : "memory");
}
#define CP_COMMIT() asm volatile("cp.async.commit_group;" ::: "memory")
#define CP_WAIT1()  asm volatile("cp.async.wait_group 1;" ::: "memory")
#define CP_WAIT0()  asm volatile("cp.async.wait_group 0;" ::: "memory")

// ---------------- init ----------------
__global__ void init_kernel() {
    int i = blockIdx.x * blockDim.x + threadIdx.x;
    if (i < N_NODES) g_count[i] = 0;
    if (i == 0) g_base = 0;
}

// ---------------- GEMM (tf32 mma.sync, cp.async double-buffered) ----------------
// 128x128 CTA tile, 8 warps 2(M)x4(N), BK=32, 2-stage pipeline.
// dyn smem: As[2][128][40] + Bs[2][32][132] floats
#define ASZ (128 * 40)
#define BSZ (32 * 132)
#define SMEM_FLOATS (2 * ASZ + 2 * BSZ)

__global__ void __launch_bounds__(256) gemm_kernel(const float* __restrict__ X,
                                                   const float* __restrict__ W,
                                                   const float* __restrict__ att_src,
                                                   const float* __restrict__ att_dst) {
    extern __shared__ float smf[];
    __shared__ float s_a[256];

    const int tid    = threadIdx.x;
    const int lane   = tid & 31;
    const int w      = tid >> 5;
    const int warp_m = w & 1;
    const int warp_n = w >> 1;
    const int gid    = lane >> 2;
    const int tig    = lane & 3;
    const int bm     = blockIdx.x * 128;

    const uint32_t smem_base = smem_u32(smf);

    // per-thread tile slots
    const int a_row = tid >> 3;            // 0..31 step: 4 rows per t
    const int a_kq  = (tid & 7) << 2;
    const int b_row = tid >> 5;
    const int b_col = (tid & 31) << 2;

    auto issue_tile = [&](int kc, int buf) {
        const int k0 = kc * 32;
#pragma unroll
        for (int t = 0; t < 4; t++) {
            int row = a_row + t * 32;
            int valid = (bm + row < N_NODES) ? 16 : 0;
            int r = (bm + row < N_NODES) ? (bm + row) : 0;
            uint32_t dst = smem_base + (uint32_t)(buf * ASZ + row * 40 + a_kq) * 4u;
            cp16(dst, &X[(size_t)r * IN_CH + k0 + a_kq], valid);
        }
#pragma unroll
        for (int t = 0; t < 4; t++) {
            int row = b_row + t * 8;
            uint32_t dst = smem_base + (uint32_t)(2 * ASZ + buf * BSZ + row * 132 + b_col) * 4u;
            cp16(dst, &W[(size_t)(32 * kc + row) * OUT_CH + b_col], 16);
        }
        CP_COMMIT();
    };

    float acc[4][4][4];
#pragma unroll
    for (int mi = 0; mi < 4; mi++)
#pragma unroll
        for (int nj = 0; nj < 4; nj++)
#pragma unroll
            for (int q = 0; q < 4; q++) acc[mi][nj][q] = 0.f;

    issue_tile(0, 0);

    for (int kc = 0; kc < 8; kc++) {
        if (kc + 1 < 8) {
            issue_tile(kc + 1, (kc + 1) & 1);
            CP_WAIT1();
        } else {
            CP_WAIT0();
        }
        __syncthreads();

        const float* As = smf + (kc & 1) * ASZ;
        const float* Bs = smf + 2 * ASZ + (kc & 1) * BSZ;

#pragma unroll
        for (int ks = 0; ks < 4; ks++) {
            const int kk = ks * 8;
            uint32_t a[4][4], b[4][2];
#pragma unroll
            for (int mi = 0; mi < 4; mi++) {
                int r = warp_m * 64 + mi * 16 + gid;
                a[mi][0] = f2tf32(As[r * 40 + kk + tig]);
                a[mi][1] = f2tf32(As[(r + 8) * 40 + kk + tig]);
                a[mi][2] = f2tf32(As[r * 40 + kk + tig + 4]);
                a[mi][3] = f2tf32(As[(r + 8) * 40 + kk + tig + 4]);
            }
#pragma unroll
            for (int nj = 0; nj < 4; nj++) {
                int cn = warp_n * 32 + nj * 8 + gid;
                b[nj][0] = f2tf32(Bs[(kk + tig) * 132 + cn]);
                b[nj][1] = f2tf32(Bs[(kk + tig + 4) * 132 + cn]);
            }
#pragma unroll
            for (int mi = 0; mi < 4; mi++)
#pragma unroll
                for (int nj = 0; nj < 4; nj++)
                    mma_tf32(acc[mi][nj], a[mi], b[nj]);
        }
        __syncthreads();
    }

    // ---- epilogue: fp16 emit + alpha logits (smem reduce) ----
    s_a[tid] = 0.f;
    __syncthreads();

    float asv[4][2], adv[4][2];
#pragma unroll
    for (int nj = 0; nj < 4; nj++) {
        int c = warp_n * 32 + nj * 8 + 2 * tig;
        asv[nj][0] = __ldg(&att_src[c]);
        asv[nj][1] = __ldg(&att_src[c + 1]);
        adv[nj][0] = __ldg(&att_dst[c]);
        adv[nj][1] = __ldg(&att_dst[c + 1]);
    }

#pragma unroll
    for (int mi = 0; mi < 4; mi++) {
        int lr0 = warp_m * 64 + mi * 16 + gid;
        int lr1 = lr0 + 8;
        int r0 = bm + lr0;
        int r1 = bm + lr1;
        float ps0 = 0.f, pd0 = 0.f, ps1 = 0.f, pd1 = 0.f;
#pragma unroll
        for (int nj = 0; nj < 4; nj++) {
            int c  = warp_n * 32 + nj * 8 + 2 * tig;
            int hc = c >> 1;
            float2 v0 = make_float2(acc[mi][nj][0], acc[mi][nj][1]);
            float2 v1 = make_float2(acc[mi][nj][2], acc[mi][nj][3]);
            if (r0 < N_NODES)
                g_xph[(size_t)r0 * (OUT_CH / 2) + hc] = __floats2half2_rn(v0.x, v0.y);
            if (r1 < N_NODES)
                g_xph[(size_t)r1 * (OUT_CH / 2) + hc] = __floats2half2_rn(v1.x, v1.y);
            ps0 += v0.x * asv[nj][0] + v0.y * asv[nj][1];
            pd0 += v0.x * adv[nj][0] + v0.y * adv[nj][1];
            ps1 += v1.x * asv[nj][0] + v1.y * asv[nj][1];
            pd1 += v1.x * adv[nj][0] + v1.y * adv[nj][1];
        }
#pragma unroll
        for (int off = 1; off < 4; off <<= 1) {
            ps0 += __shfl_xor_sync(FULL_MASK, ps0, off);
            pd0 += __shfl_xor_sync(FULL_MASK, pd0, off);
            ps1 += __shfl_xor_sync(FULL_MASK, ps1, off);
            pd1 += __shfl_xor_sync(FULL_MASK, pd1, off);
        }
        if (tig == 0) {
            atomicAdd(&s_a[lr0 * 2 + 0], ps0);
            atomicAdd(&s_a[lr0 * 2 + 1], pd0);
            atomicAdd(&s_a[lr1 * 2 + 0], ps1);
            atomicAdd(&s_a[lr1 * 2 + 1], pd1);
        }
    }
    __syncthreads();

    if (tid < 128) {
        int r = bm + tid;
        if (r < N_NODES) {
            g_asrc[r] = s_a[tid * 2 + 0];
            g_adst[r] = s_a[tid * 2 + 1];
        }
    }
}

// ---------------- histogram (drop self-edges), 4 edges/thread ----------------
__global__ void hist_kernel(const int* __restrict__ ei) {
    int t = blockIdx.x * blockDim.x + threadIdx.x;
    if (t >= N_EDGES / 4) return;
    int4 s = ((const int4*)ei)[t];
    int4 d = ((const int4*)(ei + N_EDGES))[t];
    if (s.x != d.x) atomicAdd(&g_count[d.x], 1);
    if (s.y != d.y) atomicAdd(&g_count[d.y], 1);
    if (s.z != d.z) atomicAdd(&g_count[d.z], 1);
    if (s.w != d.w) atomicAdd(&g_count[d.w], 1);
}

// ---------------- scan (warp-shuffle) ----------------
__global__ void scan_kernel() {
    __shared__ int wsum[32];
    __shared__ int sbase;
    const int tid  = threadIdx.x;
    const int lane = tid & 31;
    const int wid  = tid >> 5;
    int i = blockIdx.x * 1024 + tid;
    int c = (i < N_NODES) ? g_count[i] : 0;

    int v = c;
#pragma unroll
    for (int off = 1; off < 32; off <<= 1) {
        int t = __shfl_up_sync(FULL_MASK, v, off);
        if (lane >= off) v += t;
    }
    if (lane == 31) wsum[wid] = v;
    __syncthreads();

    if (wid == 0) {
        int s = wsum[lane];
#pragma unroll
        for (int off = 1; off < 32; off <<= 1) {
            int t = __shfl_up_sync(FULL_MASK, s, off);
            if (lane >= off) s += t;
        }
        wsum[lane] = s;
        if (lane == 31) sbase = atomicAdd(&g_base, s);
    }
    __syncthreads();

    if (i < N_NODES) {
        int prefix = (wid > 0) ? wsum[wid - 1] : 0;
        int st = sbase + prefix + v - c;
        g_start[i]  = st;
        g_cursor[i] = st;
    }
}

// ---------------- scatter into CSR, 4 edges/thread ----------------
__global__ void scatter_kernel(const int* __restrict__ ei) {
    int t = blockIdx.x * blockDim.x + threadIdx.x;
    if (t >= N_EDGES / 4) return;
    int4 s = ((const int4*)ei)[t];
    int4 d = ((const int4*)(ei + N_EDGES))[t];
    if (s.x != d.x) g_csr[atomicAdd(&g_cursor[d.x], 1)] = s.x;
    if (s.y != d.y) g_csr[atomicAdd(&g_cursor[d.y], 1)] = s.y;
    if (s.z != d.z) g_csr[atomicAdd(&g_cursor[d.z], 1)] = s.z;
    if (s.w != d.w) g_csr[atomicAdd(&g_cursor[d.w], 1)] = s.w;
}

// ---------------- fused softmax + aggregation: one warp per dst, fp16, 4x unroll ----------------
__device__ __forceinline__ void gacc(float4& acc, float wj, uint2 h) {
    float2 p0 = __half22float2(*(const __half2*)&h.x);
    float2 p1 = __half22float2(*(const __half2*)&h.y);
    acc.x += wj * p0.x;
    acc.y += wj * p0.y;
    acc.z += wj * p1.x;
    acc.w += wj * p1.y;
}

__global__ void __launch_bounds__(256) aggregate_kernel(const float* __restrict__ bias,
                                                        float* __restrict__ out) {
    int gw   = (blockIdx.x * blockDim.x + threadIdx.x) >> 5;
    int lane = threadIdx.x & 31;
    if (gw >= N_NODES) return;

    float adi = g_adst[gw];
    float asi = g_asrc[gw];

    float a0 = asi + adi;
    a0 = a0 > 0.f ? a0 : 0.2f * a0;
    float w0 = __expf(a0);

    const uint2* xph = (const uint2*)g_xph;   // 32 uint2 per row

    uint2 hs = xph[(size_t)gw * 32 + lane];
    float4 acc = make_float4(0.f, 0.f, 0.f, 0.f);
    gacc(acc, w0, hs);
    float denom_l = 0.f;

    int beg = g_start[gw];
    int cnt = g_count[gw];

    for (int base = 0; base < cnt; base += 32) {
        int e = base + lane;
        int s = 0;
        float w = 0.f;
        if (e < cnt) {
            s = g_csr[beg + e];
            float a = g_asrc[s] + adi;
            a = a > 0.f ? a : 0.2f * a;
            w = __expf(a);
        }
        denom_l += w;
        int nv = cnt - base;
        if (nv > 32) nv = 32;

        int j = 0;
        for (; j + 4 <= nv; j += 4) {
            int   s0 = __shfl_sync(FULL_MASK, s, j);
            int   s1 = __shfl_sync(FULL_MASK, s, j + 1);
            int   s2 = __shfl_sync(FULL_MASK, s, j + 2);
            int   s3 = __shfl_sync(FULL_MASK, s, j + 3);
            float w0_ = __shfl_sync(FULL_MASK, w, j);
            float w1_ = __shfl_sync(FULL_MASK, w, j + 1);
            float w2_ = __shfl_sync(FULL_MASK, w, j + 2);
            float w3_ = __shfl_sync(FULL_MASK, w, j + 3);
            uint2 h0 = xph[(size_t)s0 * 32 + lane];
            uint2 h1 = xph[(size_t)s1 * 32 + lane];
            uint2 h2 = xph[(size_t)s2 * 32 + lane];
            uint2 h3 = xph[(size_t)s3 * 32 + lane];
            gacc(acc, w0_, h0);
            gacc(acc, w1_, h1);
            gacc(acc, w2_, h2);
            gacc(acc, w3_, h3);
        }
        for (; j < nv; j++) {
            int   sj = __shfl_sync(FULL_MASK, s, j);
            float wj = __shfl_sync(FULL_MASK, w, j);
            uint2 h  = xph[(size_t)sj * 32 + lane];
            gacc(acc, wj, h);
        }
    }

#pragma unroll
    for (int off = 16; off; off >>= 1)
        denom_l += __shfl_xor_sync(FULL_MASK, denom_l, off);

    float inv = 1.f / (w0 + denom_l + 1e-16f);
    float4 b4 = ((const float4*)bias)[lane];
    float4 o  = make_float4(acc.x * inv + b4.x, acc.y * inv + b4.y,
                            acc.z * inv + b4.z, acc.w * inv + b4.w);
    ((float4*)(out + (size_t)gw * OUT_CH))[lane] = o;
}

// ---------------- launch: fork/join ----------------
extern "C" void kernel_launch(void* const* d_in, const int* in_sizes, int n_in,
                              void* d_out, int out_size) {
    const float* x       = (const float*)d_in[0];
    const int*   ei      = (const int*)d_in[1];
    const float* W       = (const float*)d_in[2];
    const float* att_src = (const float*)d_in[3];
    const float* att_dst = (const float*)d_in[4];
    const float* bias    = (const float*)d_in[5];
    float*       out     = (float*)d_out;

    (void)in_sizes; (void)n_in; (void)out_size;

    static cudaStream_t sA = nullptr, sB = nullptr;
    static cudaEvent_t  ev0 = nullptr, evA = nullptr, evB = nullptr;
    if (sA == nullptr) {
        cudaStreamCreateWithFlags(&sA, cudaStreamNonBlocking);
        cudaStreamCreateWithFlags(&sB, cudaStreamNonBlocking);
        cudaEventCreateWithFlags(&ev0, cudaEventDisableTiming);
        cudaEventCreateWithFlags(&evA, cudaEventDisableTiming);
        cudaEventCreateWithFlags(&evB, cudaEventDisableTiming);
        cudaFuncSetAttribute(gemm_kernel, cudaFuncAttributeMaxDynamicSharedMemorySize,
                             SMEM_FLOATS * 4);
    }

    // fork from origin stream
    cudaEventRecord(ev0, 0);
    cudaStreamWaitEvent(sA, ev0, 0);
    cudaStreamWaitEvent(sB, ev0, 0);

    // branch A: GEMM + fused alpha + fp16 emit
    gemm_kernel<<<(N_NODES + 127) / 128, 256, SMEM_FLOATS * 4, sA>>>(x, W, att_src, att_dst);

    // branch B: CSR build
    init_kernel<<<(N_NODES + 1023) / 1024, 1024, 0, sB>>>();
    hist_kernel<<<(N_EDGES / 4 + 255) / 256, 256, 0, sB>>>(ei);
    scan_kernel<<<(N_NODES + 1023) / 1024, 1024, 0, sB>>>();
    scatter_kernel<<<(N_EDGES / 4 + 255) / 256, 256, 0, sB>>>(ei);

    // join
    cudaEventRecord(evA, sA);
    cudaEventRecord(evB, sB);
    cudaStreamWaitEvent(0, evA, 0);
    cudaStreamWaitEvent(0, evB, 0);

    aggregate_kernel<<<(N_NODES * 32 + 255) / 256, 256>>>(bias, out);
}

// round 8
// speedup vs baseline: 2.0648x; 1.0405x over previous
#include <cuda_runtime.h>
#include <cuda_fp16.h>
#include <cstdint>

#define N_NODES 100000
#define IN_CH   256
#define OUT_CH  128
#define N_EDGES 1600000
#define FULL_MASK 0xFFFFFFFFu

// ---------------- scratch ----------------
__device__ __align__(16) __half2 g_xph[(size_t)N_NODES * (OUT_CH / 2)]; // fp16 xp
__device__ float g_asrc[N_NODES];
__device__ float g_adst[N_NODES];
__device__ int   g_count[N_NODES];
__device__ int   g_start[N_NODES];
__device__ int   g_cursor[N_NODES];
__device__ int   g_csr[N_EDGES];
__device__ int   g_base;

// ---------------- helpers ----------------
__device__ __forceinline__ uint32_t f2tf32(float v) {
    uint32_t t;
    asm("cvt.rna.tf32.f32 %0, %1;" : "=r"(t) : "f"(v));
    return t;
}
__device__ __forceinline__ void mma_tf32(float* c, const uint32_t* a, const uint32_t* b) {
    asm volatile(
        "mma.sync.aligned.m16n8k8.row.col.f32.tf32.tf32.f32 "
        "{%0,%1,%2,%3}, {%4,%5,%6,%7}, {%8,%9}, {%0,%1,%2,%3};"
        : "+f"(c[0]), "+f"(c[1]), "+f"(c[2]), "+f"(c[3])
        : "r"(a[0]), "r"(a[1]), "r"(a[2]), "r"(a[3]), "r"(b[0]), "r"(b[1]));
}
__device__ __forceinline__ uint32_t smem_u32(const void* p) {
    uint32_t a;
    asm("{ .reg .u64 t; cvta.to.shared.u64 t, %1; cvt.u32.u64 %0, t; }" : "=r"(a) : "l"(p));
    return a;
}
__device__ __forceinline__ void cp16(uint32_t dst, const void* src, int bytes) {
    asm volatile("cp.async.cg.shared.global [%0], [%1], 16, %2;"
                 :: "r"(dst), "l"(src), "r"(bytes) : "memory");
}
#define CP_COMMIT() asm volatile("cp.async.commit_group;" ::: "memory")
#define CP_WAIT1()  asm volatile("cp.async.wait_group 1;" ::: "memory")
#define CP_WAIT0()  asm volatile("cp.async.wait_group 0;" ::: "memory")

// ---------------- init ----------------
__global__ void init_kernel() {
    int i = blockIdx.x * blockDim.x + threadIdx.x;
    if (i < N_NODES) g_count[i] = 0;
    if (i == 0) g_base = 0;
}

// ---------------- GEMM (tf32 mma.sync, cp.async double-buffered) ----------------
#define ASZ (128 * 40)
#define BSZ (32 * 132)
#define SMEM_FLOATS (2 * ASZ + 2 * BSZ)

__global__ void __launch_bounds__(256) gemm_kernel(const float* __restrict__ X,
                                                   const float* __restrict__ W,
                                                   const float* __restrict__ att_src,
                                                   const float* __restrict__ att_dst) {
    extern __shared__ float smf[];
    __shared__ float s_a[256];

    const int tid    = threadIdx.x;
    const int lane   = tid & 31;
    const int w      = tid >> 5;
    const int warp_m = w & 1;
    const int warp_n = w >> 1;
    const int gid    = lane >> 2;
    const int tig    = lane & 3;
    const int bm     = blockIdx.x * 128;

    const uint32_t smem_base = smem_u32(smf);

    const int a_row = tid >> 3;
    const int a_kq  = (tid & 7) << 2;
    const int b_row = tid >> 5;
    const int b_col = (tid & 31) << 2;

    auto issue_tile = [&](int kc, int buf) {
        const int k0 = kc * 32;
#pragma unroll
        for (int t = 0; t < 4; t++) {
            int row = a_row + t * 32;
            int valid = (bm + row < N_NODES) ? 16 : 0;
            int r = (bm + row < N_NODES) ? (bm + row) : 0;
            uint32_t dst = smem_base + (uint32_t)(buf * ASZ + row * 40 + a_kq) * 4u;
            cp16(dst, &X[(size_t)r * IN_CH + k0 + a_kq], valid);
        }
#pragma unroll
        for (int t = 0; t < 4; t++) {
            int row = b_row + t * 8;
            uint32_t dst = smem_base + (uint32_t)(2 * ASZ + buf * BSZ + row * 132 + b_col) * 4u;
            cp16(dst, &W[(size_t)(32 * kc + row) * OUT_CH + b_col], 16);
        }
        CP_COMMIT();
    };

    float acc[4][4][4];
#pragma unroll
    for (int mi = 0; mi < 4; mi++)
#pragma unroll
        for (int nj = 0; nj < 4; nj++)
#pragma unroll
            for (int q = 0; q < 4; q++) acc[mi][nj][q] = 0.f;

    issue_tile(0, 0);

    for (int kc = 0; kc < 8; kc++) {
        if (kc + 1 < 8) {
            issue_tile(kc + 1, (kc + 1) & 1);
            CP_WAIT1();
        } else {
            CP_WAIT0();
        }
        __syncthreads();

        const float* As = smf + (kc & 1) * ASZ;
        const float* Bs = smf + 2 * ASZ + (kc & 1) * BSZ;

#pragma unroll
        for (int ks = 0; ks < 4; ks++) {
            const int kk = ks * 8;
            uint32_t a[4][4], b[4][2];
#pragma unroll
            for (int mi = 0; mi < 4; mi++) {
                int r = warp_m * 64 + mi * 16 + gid;
                a[mi][0] = f2tf32(As[r * 40 + kk + tig]);
                a[mi][1] = f2tf32(As[(r + 8) * 40 + kk + tig]);
                a[mi][2] = f2tf32(As[r * 40 + kk + tig + 4]);
                a[mi][3] = f2tf32(As[(r + 8) * 40 + kk + tig + 4]);
            }
#pragma unroll
            for (int nj = 0; nj < 4; nj++) {
                int cn = warp_n * 32 + nj * 8 + gid;
                b[nj][0] = f2tf32(Bs[(kk + tig) * 132 + cn]);
                b[nj][1] = f2tf32(Bs[(kk + tig + 4) * 132 + cn]);
            }
#pragma unroll
            for (int mi = 0; mi < 4; mi++)
#pragma unroll
                for (int nj = 0; nj < 4; nj++)
                    mma_tf32(acc[mi][nj], a[mi], b[nj]);
        }
        __syncthreads();
    }

    // ---- epilogue: fp16 emit + alpha logits (smem reduce) ----
    s_a[tid] = 0.f;
    __syncthreads();

    float asv[4][2], adv[4][2];
#pragma unroll
    for (int nj = 0; nj < 4; nj++) {
        int c = warp_n * 32 + nj * 8 + 2 * tig;
        asv[nj][0] = __ldg(&att_src[c]);
        asv[nj][1] = __ldg(&att_src[c + 1]);
        adv[nj][0] = __ldg(&att_dst[c]);
        adv[nj][1] = __ldg(&att_dst[c + 1]);
    }

#pragma unroll
    for (int mi = 0; mi < 4; mi++) {
        int lr0 = warp_m * 64 + mi * 16 + gid;
        int lr1 = lr0 + 8;
        int r0 = bm + lr0;
        int r1 = bm + lr1;
        float ps0 = 0.f, pd0 = 0.f, ps1 = 0.f, pd1 = 0.f;
#pragma unroll
        for (int nj = 0; nj < 4; nj++) {
            int c  = warp_n * 32 + nj * 8 + 2 * tig;
            int hc = c >> 1;
            float2 v0 = make_float2(acc[mi][nj][0], acc[mi][nj][1]);
            float2 v1 = make_float2(acc[mi][nj][2], acc[mi][nj][3]);
            if (r0 < N_NODES)
                g_xph[(size_t)r0 * (OUT_CH / 2) + hc] = __floats2half2_rn(v0.x, v0.y);
            if (r1 < N_NODES)
                g_xph[(size_t)r1 * (OUT_CH / 2) + hc] = __floats2half2_rn(v1.x, v1.y);
            ps0 += v0.x * asv[nj][0] + v0.y * asv[nj][1];
            pd0 += v0.x * adv[nj][0] + v0.y * adv[nj][1];
            ps1 += v1.x * asv[nj][0] + v1.y * asv[nj][1];
            pd1 += v1.x * adv[nj][0] + v1.y * adv[nj][1];
        }
#pragma unroll
        for (int off = 1; off < 4; off <<= 1) {
            ps0 += __shfl_xor_sync(FULL_MASK, ps0, off);
            pd0 += __shfl_xor_sync(FULL_MASK, pd0, off);
            ps1 += __shfl_xor_sync(FULL_MASK, ps1, off);
            pd1 += __shfl_xor_sync(FULL_MASK, pd1, off);
        }
        if (tig == 0) {
            atomicAdd(&s_a[lr0 * 2 + 0], ps0);
            atomicAdd(&s_a[lr0 * 2 + 1], pd0);
            atomicAdd(&s_a[lr1 * 2 + 0], ps1);
            atomicAdd(&s_a[lr1 * 2 + 1], pd1);
        }
    }
    __syncthreads();

    if (tid < 128) {
        int r = bm + tid;
        if (r < N_NODES) {
            g_asrc[r] = s_a[tid * 2 + 0];
            g_adst[r] = s_a[tid * 2 + 1];
        }
    }
}

// ---------------- histogram (drop self-edges), 4 edges/thread ----------------
__global__ void hist_kernel(const int* __restrict__ ei) {
    int t = blockIdx.x * blockDim.x + threadIdx.x;
    if (t >= N_EDGES / 4) return;
    int4 s = ((const int4*)ei)[t];
    int4 d = ((const int4*)(ei + N_EDGES))[t];
    if (s.x != d.x) atomicAdd(&g_count[d.x], 1);
    if (s.y != d.y) atomicAdd(&g_count[d.y], 1);
    if (s.z != d.z) atomicAdd(&g_count[d.z], 1);
    if (s.w != d.w) atomicAdd(&g_count[d.w], 1);
}

// ---------------- scan (warp-shuffle) ----------------
__global__ void scan_kernel() {
    __shared__ int wsum[32];
    __shared__ int sbase;
    const int tid  = threadIdx.x;
    const int lane = tid & 31;
    const int wid  = tid >> 5;
    int i = blockIdx.x * 1024 + tid;
    int c = (i < N_NODES) ? g_count[i] : 0;

    int v = c;
#pragma unroll
    for (int off = 1; off < 32; off <<= 1) {
        int t = __shfl_up_sync(FULL_MASK, v, off);
        if (lane >= off) v += t;
    }
    if (lane == 31) wsum[wid] = v;
    __syncthreads();

    if (wid == 0) {
        int s = wsum[lane];
#pragma unroll
        for (int off = 1; off < 32; off <<= 1) {
            int t = __shfl_up_sync(FULL_MASK, s, off);
            if (lane >= off) s += t;
        }
        wsum[lane] = s;
        if (lane == 31) sbase = atomicAdd(&g_base, s);
    }
    __syncthreads();

    if (i < N_NODES) {
        int prefix = (wid > 0) ? wsum[wid - 1] : 0;
        int st = sbase + prefix + v - c;
        g_start[i]  = st;
        g_cursor[i] = st;
    }
}

// ---------------- scatter into CSR, 4 edges/thread ----------------
__global__ void scatter_kernel(const int* __restrict__ ei) {
    int t = blockIdx.x * blockDim.x + threadIdx.x;
    if (t >= N_EDGES / 4) return;
    int4 s = ((const int4*)ei)[t];
    int4 d = ((const int4*)(ei + N_EDGES))[t];
    if (s.x != d.x) g_csr[atomicAdd(&g_cursor[d.x], 1)] = s.x;
    if (s.y != d.y) g_csr[atomicAdd(&g_cursor[d.y], 1)] = s.y;
    if (s.z != d.z) g_csr[atomicAdd(&g_cursor[d.z], 1)] = s.z;
    if (s.w != d.w) g_csr[atomicAdd(&g_cursor[d.w], 1)] = s.w;
}

// ---------------- fused softmax + aggregation ----------------
// One warp per dst node; half-warp edge parallelism: lanes 0-15 -> edge j,
// lanes 16-31 -> edge j+1. Each lane covers 8 channels via one LDG.128.
__device__ __forceinline__ void acc8(float* acc, float wj, uint4 h) {
    float2 p0 = __half22float2(*(const __half2*)&h.x);
    float2 p1 = __half22float2(*(const __half2*)&h.y);
    float2 p2 = __half22float2(*(const __half2*)&h.z);
    float2 p3 = __half22float2(*(const __half2*)&h.w);
    acc[0] += wj * p0.x;  acc[1] += wj * p0.y;
    acc[2] += wj * p1.x;  acc[3] += wj * p1.y;
    acc[4] += wj * p2.x;  acc[5] += wj * p2.y;
    acc[6] += wj * p3.x;  acc[7] += wj * p3.y;
}

__global__ void __launch_bounds__(256) aggregate_kernel(const float* __restrict__ bias,
                                                        float* __restrict__ out) {
    int gw   = (blockIdx.x * blockDim.x + threadIdx.x) >> 5;
    int lane = threadIdx.x & 31;
    if (gw >= N_NODES) return;

    const int half = lane >> 4;     // 0 or 1
    const int lc   = lane & 15;     // channel-group id (8 channels each)

    float adi = g_adst[gw];
    float asi = g_asrc[gw];

    float a0 = asi + adi;
    a0 = a0 > 0.f ? a0 : 0.2f * a0;
    float w0 = __expf(a0);

    const uint4* xph16 = (const uint4*)g_xph;   // 16 uint4 per row

    float acc[8];
#pragma unroll
    for (int q = 0; q < 8; q++) acc[q] = 0.f;
    float denom_l = 0.f;

    int beg = g_start[gw];
    int cnt = g_count[gw];

    for (int base = 0; base < cnt; base += 32) {
        int e = base + lane;
        int s = 0;
        float w = 0.f;
        if (e < cnt) {
            s = g_csr[beg + e];
            float a = g_asrc[s] + adi;
            a = a > 0.f ? a : 0.2f * a;
            w = __expf(a);
        }
        denom_l += w;
        int nv = cnt - base;
        if (nv > 32) nv = 32;

        int j = 0;
        // 4 edges per iteration: 2 per half-warp, 2 LDG.128 in flight per lane
        for (; j + 4 <= nv; j += 4) {
            int j0 = j + half;
            int j1 = j + 2 + half;
            int   s0 = __shfl_sync(FULL_MASK, s, j0);
            int   s1 = __shfl_sync(FULL_MASK, s, j1);
            float u0 = __shfl_sync(FULL_MASK, w, j0);
            float u1 = __shfl_sync(FULL_MASK, w, j1);
            uint4 h0 = xph16[(size_t)s0 * 16 + lc];
            uint4 h1 = xph16[(size_t)s1 * 16 + lc];
            acc8(acc, u0, h0);
            acc8(acc, u1, h1);
        }
        // tail: 2 edges per iteration (second may be invalid)
        for (; j < nv; j += 2) {
            int jj = j + half;
            int   sj = __shfl_sync(FULL_MASK, s, jj & 31);
            float wj = __shfl_sync(FULL_MASK, w, jj & 31);
            if (jj >= nv) wj = 0.f;
            uint4 h = xph16[(size_t)sj * 16 + lc];
            acc8(acc, wj, h);
        }
    }

    // fold the two half-warp accumulators (lane i += lane i+16)
#pragma unroll
    for (int q = 0; q < 8; q++)
        acc[q] += __shfl_xor_sync(FULL_MASK, acc[q], 16);

#pragma unroll
    for (int off = 16; off; off >>= 1)
        denom_l += __shfl_xor_sync(FULL_MASK, denom_l, off);

    // self-loop term + output (lanes 0-15 hold the full sums)
    uint4 hs = xph16[(size_t)gw * 16 + lc];
    if (half == 0) {
        acc8(acc, w0, hs);
        float inv = 1.f / (w0 + denom_l + 1e-16f);
        float4 b0 = ((const float4*)bias)[lc * 2];
        float4 b1 = ((const float4*)bias)[lc * 2 + 1];
        float4 o0 = make_float4(acc[0] * inv + b0.x, acc[1] * inv + b0.y,
                                acc[2] * inv + b0.z, acc[3] * inv + b0.w);
        float4 o1 = make_float4(acc[4] * inv + b1.x, acc[5] * inv + b1.y,
                                acc[6] * inv + b1.z, acc[7] * inv + b1.w);
        ((float4*)(out + (size_t)gw * OUT_CH))[lc * 2]     = o0;
        ((float4*)(out + (size_t)gw * OUT_CH))[lc * 2 + 1] = o1;
    }
}

// ---------------- launch: fork/join ----------------
extern "C" void kernel_launch(void* const* d_in, const int* in_sizes, int n_in,
                              void* d_out, int out_size) {
    const float* x       = (const float*)d_in[0];
    const int*   ei      = (const int*)d_in[1];
    const float* W       = (const float*)d_in[2];
    const float* att_src = (const float*)d_in[3];
    const float* att_dst = (const float*)d_in[4];
    const float* bias    = (const float*)d_in[5];
    float*       out     = (float*)d_out;

    (void)in_sizes; (void)n_in; (void)out_size;

    static cudaStream_t sA = nullptr, sB = nullptr;
    static cudaEvent_t  ev0 = nullptr, evA = nullptr, evB = nullptr;
    if (sA == nullptr) {
        cudaStreamCreateWithFlags(&sA, cudaStreamNonBlocking);
        cudaStreamCreateWithFlags(&sB, cudaStreamNonBlocking);
        cudaEventCreateWithFlags(&ev0, cudaEventDisableTiming);
        cudaEventCreateWithFlags(&evA, cudaEventDisableTiming);
        cudaEventCreateWithFlags(&evB, cudaEventDisableTiming);
        cudaFuncSetAttribute(gemm_kernel, cudaFuncAttributeMaxDynamicSharedMemorySize,
                             SMEM_FLOATS * 4);
    }

    // fork from origin stream
    cudaEventRecord(ev0, 0);
    cudaStreamWaitEvent(sA, ev0, 0);
    cudaStreamWaitEvent(sB, ev0, 0);

    // branch A: GEMM + fused alpha + fp16 emit
    gemm_kernel<<<(N_NODES + 127) / 128, 256, SMEM_FLOATS * 4, sA>>>(x, W, att_src, att_dst);

    // branch B: CSR build
    init_kernel<<<(N_NODES + 1023) / 1024, 1024, 0, sB>>>();
    hist_kernel<<<(N_EDGES / 4 + 255) / 256, 256, 0, sB>>>(ei);
    scan_kernel<<<(N_NODES + 1023) / 1024, 1024, 0, sB>>>();
    scatter_kernel<<<(N_EDGES / 4 + 255) / 256, 256, 0, sB>>>(ei);

    // join
    cudaEventRecord(evA, sA);
    cudaEventRecord(evB, sB);
    cudaStreamWaitEvent(0, evA, 0);
    cudaStreamWaitEvent(0, evB, 0);

    aggregate_kernel<<<(N_NODES * 32 + 255) / 256, 256>>>(bias, out);
}